// round 13
// baseline (speedup 1.0000x reference)
#include <cuda_runtime.h>
#include <cuda_fp16.h>
#include <cstdint>

// ---------------- Problem constants ----------------
#define N_ROWS     262144
#define K_CODES    1024
#define D_DIM      64
#define M_TILE     128                  // rows per CTA
#define CHUNK      64                   // codes per chunk
#define NUM_CHUNKS (K_CODES / CHUNK)    // 16
#define KCOLS      64                   // fp16 codebook cols
#define NUM_KS     (KCOLS / 16)         // 4
#define ROWB       144                  // A smem row stride bytes (LDSM conflict-free)
#define TAU        1.2e-3f              // certification threshold

// ---------------- Static scratch ----------------
__device__ float g_csq[K_CODES];
__device__ float g_Ct[D_DIM * K_CODES];                 // transposed codebook (d-major)
// B in HMMA fragment order: [gtile(128)][half(2)][lane(32)] x uint4
__device__ __align__(16) uint32_t g_Bfrag[(K_CODES / 8) * 2 * 32 * 4];

// ---------------- Helpers ----------------
__device__ __forceinline__ uint32_t smem_u32(const void* p) {
    uint32_t a;
    asm("{ .reg .u64 t; cvta.to.shared.u64 t, %1; cvt.u32.u64 %0, t; }" : "=r"(a) : "l"(p));
    return a;
}
#define LDSM4(r0, r1, r2, r3, a)                                                    \
    asm volatile("ldmatrix.sync.aligned.m8n8.x4.shared.b16 {%0,%1,%2,%3}, [%4];"    \
                 : "=r"(r0), "=r"(r1), "=r"(r2), "=r"(r3) : "r"(a))
#define MMA16816(d, a, b0v, b1v)                                                    \
    asm volatile("mma.sync.aligned.m16n8k16.row.col.f32.f16.f16.f32 "               \
                 "{%0,%1,%2,%3},{%4,%5,%6,%7},{%8,%9},{%0,%1,%2,%3};"               \
                 : "+f"((d)[0]), "+f"((d)[1]), "+f"((d)[2]), "+f"((d)[3])           \
                 : "r"((a)[0]), "r"((a)[1]), "r"((a)[2]), "r"((a)[3]),              \
                   "r"(b0v), "r"(b1v))

__device__ __forceinline__ uint32_t pack_h2(float a, float b) {
    __half2 t(__float2half_rn(a), __float2half_rn(b));
    return *reinterpret_cast<uint32_t*>(&t);
}

// ---------------- Exact reference-order arithmetic (bit-validated R3/R5/R6/R8/R12) ----------------
__device__ __forceinline__ float sq_sum_tree64(const float* v) {
    float s[32];
#pragma unroll
    for (int l = 0; l < 32; l++) {
        float a = v[l], b = v[l + 32];
        s[l] = __fadd_rn(__fmul_rn(a, a), __fmul_rn(b, b));
    }
#pragma unroll
    for (int off = 16; off >= 1; off >>= 1)
#pragma unroll
        for (int l = 0; l < 16; l++)
            if (l < off) s[l] = __fadd_rn(s[l], s[l + off]);
    return s[0];
}

// ---------------- Prep: exact csq + transposed copy ----------------
__global__ void prep_kernel(const float* __restrict__ Cb) {
    int k = blockIdx.x * blockDim.x + threadIdx.x;
    if (k >= K_CODES) return;
    const float* c = Cb + (size_t)k * D_DIM;
    g_csq[k] = sq_sum_tree64(c);
#pragma unroll 8
    for (int d = 0; d < D_DIM; d++)
        g_Ct[d * K_CODES + k] = c[d];   // d-major for coalesced exact rescore
}

// ---------------- Prep: fp16 codebook in m16n8k16 B-fragment order ----------------
__global__ void prep_frag_kernel(const float* __restrict__ Cb) {
    int tid = blockIdx.x * blockDim.x + threadIdx.x;   // 0..4095
    int gt = tid >> 5, l = tid & 31;
    int code = gt * 8 + (l >> 2);
    int kb = 2 * (l & 3);
    const float* cr = Cb + (size_t)code * D_DIM;
    uint32_t f[8];
#pragma unroll
    for (int ks = 0; ks < 4; ks++) {
        float2 v0 = *reinterpret_cast<const float2*>(cr + ks * 16 + kb);
        float2 v1 = *reinterpret_cast<const float2*>(cr + ks * 16 + kb + 8);
        f[ks * 2 + 0] = pack_h2(v0.x, v0.y);
        f[ks * 2 + 1] = pack_h2(v1.x, v1.y);
    }
    uint4* dst = reinterpret_cast<uint4*>(g_Bfrag);
    dst[(gt * 2 + 0) * 32 + l] = make_uint4(f[0], f[1], f[2], f[3]);
    dst[(gt * 2 + 1) * 32 + l] = make_uint4(f[4], f[5], f[6], f[7]);
}

// ---------------- Screen kernel with fused exact-rescore tail ----------------
#define SM_A     0u                     // 128 x 144B = 18432
#define SM_HC    18432u                 // 1024 f32 = 4096 (-0.5*csq)
#define SM_BK    22528u                 // 128 i32
#define SM_XR    23040u                 // 64 f32 exact row
#define SM_XQ    23296u                 // 1 f32 exact xsq
#define SM_RS    23312u                 // 8 f32 per-warp best score
#define SM_RK    23344u                 // 8 i32 per-warp best k
#define SM_NF    23376u                 // 1 i32 flag count
#define SM_FL    23380u                 // 128 i32 flagged local rows
#define SM_TOTAL 23936u

extern "C" __global__ void __launch_bounds__(256, 2)
vq_screen_kernel(const float* __restrict__ X, const float* __restrict__ Cb,
                 float* __restrict__ out_idx, float* __restrict__ out_res,
                 float* __restrict__ out_cb) {
    extern __shared__ __align__(128) char smem[];
    const uint32_t sb = smem_u32(smem);
    const int t = threadIdx.x;
    const int w = t >> 5, l = t & 31;
    const int wr0 = w * 16;
    const int m0 = blockIdx.x * M_TILE;
    int* best_sh = (int*)(smem + SM_BK);
    int* s_nf = (int*)(smem + SM_NF);
    int* s_fl = (int*)(smem + SM_FL);

    if (t == 0) *s_nf = 0;
    {
        const float4* X4 = (const float4*)(X + (size_t)m0 * D_DIM);
#pragma unroll
        for (int i = 0; i < 8; i++) {
            int f = t + i * 256;
            int row = f >> 4, d = (f & 15) * 4;
            float4 v = X4[f];
            uint2 hv = make_uint2(pack_h2(v.x, v.y), pack_h2(v.z, v.w));
            *reinterpret_cast<uint2*>(smem + SM_A + row * ROWB + d * 2) = hv;
        }
        float* hc = (float*)(smem + SM_HC);
        for (int i = t; i < K_CODES; i += 256) hc[i] = -0.5f * g_csq[i];
    }
    __syncthreads();

    uint32_t af[NUM_KS][4];
    {
        uint32_t aAddr = sb + SM_A + (uint32_t)(wr0 + (l & 15)) * ROWB + (uint32_t)(l >> 4) * 16;
#pragma unroll
        for (int ks = 0; ks < NUM_KS; ks++)
            LDSM4(af[ks][0], af[ks][1], af[ks][2], af[ks][3], aAddr + ks * 32);
    }

    float bmA1 = -3.0e38f, bmA2 = -3.0e38f, bmB1 = -3.0e38f, bmB2 = -3.0e38f;
    int bkA = 0, bkB = 0;
    const float* hc = (const float*)(smem + SM_HC);

    for (int c = 0; c < NUM_CHUNKS; c++) {
        float acc[8][4];
#pragma unroll
        for (int nt = 0; nt < 8; nt++)
#pragma unroll
            for (int j = 0; j < 4; j++) acc[nt][j] = 0.f;

        const uint4* bf = reinterpret_cast<const uint4*>(g_Bfrag) + (size_t)c * 8 * 2 * 32 + l;
#pragma unroll
        for (int nt = 0; nt < 8; nt++) {
            uint4 f0 = __ldg(bf + (nt * 2 + 0) * 32);
            uint4 f1 = __ldg(bf + (nt * 2 + 1) * 32);
            MMA16816(acc[nt], af[0], f0.x, f0.y);
            MMA16816(acc[nt], af[1], f0.z, f0.w);
            MMA16816(acc[nt], af[2], f1.x, f1.y);
            MMA16816(acc[nt], af[3], f1.z, f1.w);
        }

#pragma unroll
        for (int nt = 0; nt < 8; nt++) {
            int k0 = c * CHUNK + nt * 8 + (l & 3) * 2;
            float2 hcv = *reinterpret_cast<const float2*>(hc + k0);
            float v0 = acc[nt][0] + hcv.x, v1 = acc[nt][1] + hcv.y;
            float v2 = acc[nt][2] + hcv.x, v3 = acc[nt][3] + hcv.y;
            if (v0 > bmA1) { bmA2 = bmA1; bmA1 = v0; bkA = k0; }     else bmA2 = fmaxf(bmA2, v0);
            if (v1 > bmA1) { bmA2 = bmA1; bmA1 = v1; bkA = k0 + 1; } else bmA2 = fmaxf(bmA2, v1);
            if (v2 > bmB1) { bmB2 = bmB1; bmB1 = v2; bkB = k0; }     else bmB2 = fmaxf(bmB2, v2);
            if (v3 > bmB1) { bmB2 = bmB1; bmB1 = v3; bkB = k0 + 1; } else bmB2 = fmaxf(bmB2, v3);
        }
    }

#pragma unroll
    for (int off = 1; off <= 2; off <<= 1) {
        float o1, o2; int ok;
        o1 = __shfl_xor_sync(0xffffffffu, bmA1, off);
        o2 = __shfl_xor_sync(0xffffffffu, bmA2, off);
        ok = __shfl_xor_sync(0xffffffffu, bkA, off);
        {
            bool bw = (o1 > bmA1) || (o1 == bmA1 && ok < bkA);
            float n2 = fmaxf(fminf(bmA1, o1), fmaxf(bmA2, o2));
            if (bw) { bmA1 = o1; bkA = ok; }
            bmA2 = n2;
        }
        o1 = __shfl_xor_sync(0xffffffffu, bmB1, off);
        o2 = __shfl_xor_sync(0xffffffffu, bmB2, off);
        ok = __shfl_xor_sync(0xffffffffu, bkB, off);
        {
            bool bw = (o1 > bmB1) || (o1 == bmB1 && ok < bkB);
            float n2 = fmaxf(fminf(bmB1, o1), fmaxf(bmB2, o2));
            if (bw) { bmB1 = o1; bkB = ok; }
            bmB2 = n2;
        }
    }
    if ((l & 3) == 0) {
        int rowA = wr0 + (l >> 2);
        int rowB = rowA + 8;
        best_sh[rowA] = bkA;
        best_sh[rowB] = bkB;
        if (bmA1 - bmA2 <= TAU) { int a = atomicAdd(s_nf, 1); s_fl[a] = rowA; }
        if (bmB1 - bmB2 <= TAU) { int a = atomicAdd(s_nf, 1); s_fl[a] = rowB; }
    }
    __syncthreads();

    // ---- fused exact rescore for flagged rows (bit-validated arithmetic) ----
    {
        const int nf = *s_nf;
        float* xr = (float*)(smem + SM_XR);
        float* xq = (float*)(smem + SM_XQ);
        float* rs = (float*)(smem + SM_RS);
        int*   rk = (int*)(smem + SM_RK);
        for (int r = 0; r < nf; r++) {
            const int row = s_fl[r];
            if (t < D_DIM) xr[t] = X[(size_t)(m0 + row) * D_DIM + t];
            __syncthreads();
            if (t == 0) *xq = sq_sum_tree64(xr);
            __syncthreads();
            const float xsq = *xq;
            float bs = 3.0e38f;
            int bk = 0;
#pragma unroll
            for (int c = 0; c < K_CODES / 256; c++) {   // per-thread k ascending
                int k = c * 256 + t;
                float acc = 0.f;
#pragma unroll 8
                for (int d = 0; d < D_DIM; d++)
                    acc = fmaf(xr[d], __ldg(&g_Ct[d * K_CODES + k]), acc);
                float s = __fadd_rn(__fsub_rn(xsq, 2.0f * acc), g_csq[k]);
                if (s < bs) { bs = s; bk = k; }          // strict <: lowest k per thread
            }
#pragma unroll
            for (int off = 16; off; off >>= 1) {         // lowest k on exact ties
                float os = __shfl_xor_sync(0xffffffffu, bs, off);
                int ok = __shfl_xor_sync(0xffffffffu, bk, off);
                if (os < bs || (os == bs && ok < bk)) { bs = os; bk = ok; }
            }
            if (l == 0) { rs[w] = bs; rk[w] = bk; }
            __syncthreads();
            if (t == 0) {
                float fbs = rs[0]; int fbk = rk[0];
                for (int wi = 1; wi < 8; wi++)
                    if (rs[wi] < fbs || (rs[wi] == fbs && rk[wi] < fbk)) {
                        fbs = rs[wi]; fbk = rk[wi];
                    }
                best_sh[row] = fbk;
            }
            __syncthreads();
        }
    }

    // ---- outputs: idx + gather + residual (winners now final) ----
    if (t < M_TILE) out_idx[m0 + t] = (float)best_sh[t];
#pragma unroll
    for (int i = 0; i < (M_TILE * D_DIM) / 256; i++) {
        int f = t + i * 256;
        int row = f >> 6, d = f & 63;
        int bk = best_sh[row];
        size_t g = (size_t)(m0 + row) * D_DIM + d;
        float cv = __ldg(&Cb[(size_t)bk * D_DIM + d]);
        float xv = __ldg(&X[g]);
        out_cb[g]  = cv;
        out_res[g] = __fsub_rn(xv, cv);
    }
}

// ---------------- Launch ----------------
extern "C" void kernel_launch(void* const* d_in, const int* in_sizes, int n_in,
                              void* d_out, int out_size) {
    const float* X = (const float*)d_in[0];
    const float* C = (const float*)d_in[1];
    float* out_idx = (float*)d_out;
    float* out_res = out_idx + N_ROWS;
    float* out_cb  = out_res + (size_t)N_ROWS * D_DIM;

    cudaFuncSetAttribute(vq_screen_kernel,
                         cudaFuncAttributeMaxDynamicSharedMemorySize, SM_TOTAL);

    prep_kernel<<<(K_CODES + 255) / 256, 256>>>(C);
    prep_frag_kernel<<<16, 256>>>(C);
    vq_screen_kernel<<<N_ROWS / M_TILE, 256, SM_TOTAL>>>(X, C, out_idx, out_res, out_cb);
}

// round 14
// speedup vs baseline: 1.3542x; 1.3542x over previous
#include <cuda_runtime.h>
#include <cuda_fp16.h>
#include <cstdint>

// ---------------- Problem constants ----------------
#define N_ROWS     262144
#define K_CODES    1024
#define D_DIM      64
#define M_TILE     128                  // rows per CTA
#define CHUNK      64                   // codes per chunk
#define NUM_CHUNKS (K_CODES / CHUNK)    // 16
#define KCOLS      64                   // fp16 codebook cols
#define NUM_KS     (KCOLS / 16)         // 4
#define ROWB       144                  // A smem row stride bytes (LDSM conflict-free)
#define TAU        1.2e-3f              // certification threshold

// ---------------- Static scratch ----------------
__device__ float g_csq[K_CODES];
__device__ float g_Ct[D_DIM * K_CODES];                 // transposed codebook (d-major)
// B in HMMA fragment order: [gtile(128)][half(2)][lane(32)] x uint4
__device__ __align__(16) uint32_t g_Bfrag[(K_CODES / 8) * 2 * 32 * 4];
__device__ int g_namb;
__device__ int g_amb_rows[N_ROWS];

// ---------------- Helpers ----------------
__device__ __forceinline__ uint32_t smem_u32(const void* p) {
    uint32_t a;
    asm("{ .reg .u64 t; cvta.to.shared.u64 t, %1; cvt.u32.u64 %0, t; }" : "=r"(a) : "l"(p));
    return a;
}
#define LDSM4(r0, r1, r2, r3, a)                                                    \
    asm volatile("ldmatrix.sync.aligned.m8n8.x4.shared.b16 {%0,%1,%2,%3}, [%4];"    \
                 : "=r"(r0), "=r"(r1), "=r"(r2), "=r"(r3) : "r"(a))
#define MMA16816(d, a, b0v, b1v)                                                    \
    asm volatile("mma.sync.aligned.m16n8k16.row.col.f32.f16.f16.f32 "               \
                 "{%0,%1,%2,%3},{%4,%5,%6,%7},{%8,%9},{%0,%1,%2,%3};"               \
                 : "+f"((d)[0]), "+f"((d)[1]), "+f"((d)[2]), "+f"((d)[3])           \
                 : "r"((a)[0]), "r"((a)[1]), "r"((a)[2]), "r"((a)[3]),              \
                   "r"(b0v), "r"(b1v))

__device__ __forceinline__ uint32_t pack_h2(float a, float b) {
    __half2 t(__float2half_rn(a), __float2half_rn(b));
    return *reinterpret_cast<uint32_t*>(&t);
}

// ---------------- Exact reference-order arithmetic (bit-validated R3/R5/R6/R8/R12) ----------------
__device__ __forceinline__ float sq_sum_tree64(const float* v) {
    float s[32];
#pragma unroll
    for (int l = 0; l < 32; l++) {
        float a = v[l], b = v[l + 32];
        s[l] = __fadd_rn(__fmul_rn(a, a), __fmul_rn(b, b));
    }
#pragma unroll
    for (int off = 16; off >= 1; off >>= 1)
#pragma unroll
        for (int l = 0; l < 16; l++)
            if (l < off) s[l] = __fadd_rn(s[l], s[l + off]);
    return s[0];
}

// ---------------- Prep A: exact csq (validated tree) + zero amb counter ----------------
__global__ void prep_csq_kernel(const float* __restrict__ Cb) {
    int k = blockIdx.x * blockDim.x + threadIdx.x;
    if (k == 0) g_namb = 0;
    if (k >= K_CODES) return;
    g_csq[k] = sq_sum_tree64(Cb + (size_t)k * D_DIM);
}

// ---------------- Prep B: tiled transpose Cb[k][d] -> g_Ct[d][k], both sides coalesced ----------------
__global__ void prep_transpose_kernel(const float* __restrict__ Cb) {
    __shared__ float tile[32][33];
    const int k0 = blockIdx.x * 32;     // 32 tiles over K
    const int d0 = blockIdx.y * 32;     // 2 tiles over D
    const int x = threadIdx.x, y = threadIdx.y;
#pragma unroll
    for (int j = 0; j < 32; j += 8)
        tile[y + j][x] = Cb[(size_t)(k0 + y + j) * D_DIM + d0 + x];
    __syncthreads();
#pragma unroll
    for (int j = 0; j < 32; j += 8)
        g_Ct[(d0 + y + j) * K_CODES + k0 + x] = tile[x][y + j];
}

// ---------------- Prep C: fp16 codebook in m16n8k16 B-fragment order ----------------
__global__ void prep_frag_kernel(const float* __restrict__ Cb) {
    int tid = blockIdx.x * blockDim.x + threadIdx.x;   // 0..4095
    int gt = tid >> 5, l = tid & 31;
    int code = gt * 8 + (l >> 2);
    int kb = 2 * (l & 3);
    const float* cr = Cb + (size_t)code * D_DIM;
    uint32_t f[8];
#pragma unroll
    for (int ks = 0; ks < 4; ks++) {
        float2 v0 = *reinterpret_cast<const float2*>(cr + ks * 16 + kb);
        float2 v1 = *reinterpret_cast<const float2*>(cr + ks * 16 + kb + 8);
        f[ks * 2 + 0] = pack_h2(v0.x, v0.y);
        f[ks * 2 + 1] = pack_h2(v1.x, v1.y);
    }
    uint4* dst = reinterpret_cast<uint4*>(g_Bfrag);
    dst[(gt * 2 + 0) * 32 + l] = make_uint4(f[0], f[1], f[2], f[3]);
    dst[(gt * 2 + 1) * 32 + l] = make_uint4(f[4], f[5], f[6], f[7]);
}

// ---------------- Screen kernel (identical to passing R8/R12, best measured) ----------------
#define SM_A   0u                       // 128 x 144B = 18432
#define SM_HC  18432u                   // 1024 f32 = 4096 (-0.5*csq)
#define SM_BK  22528u                   // 128 i32
#define SM_TOTAL 23040u

extern "C" __global__ void __launch_bounds__(256, 2)
vq_screen_kernel(const float* __restrict__ X, const float* __restrict__ Cb,
                 float* __restrict__ out_idx, float* __restrict__ out_res,
                 float* __restrict__ out_cb) {
    extern __shared__ __align__(128) char smem[];
    const uint32_t sb = smem_u32(smem);
    const int t = threadIdx.x;
    const int w = t >> 5, l = t & 31;
    const int wr0 = w * 16;
    const int m0 = blockIdx.x * M_TILE;
    int* best_sh = (int*)(smem + SM_BK);

    {
        const float4* X4 = (const float4*)(X + (size_t)m0 * D_DIM);
#pragma unroll
        for (int i = 0; i < 8; i++) {
            int f = t + i * 256;
            int row = f >> 4, d = (f & 15) * 4;
            float4 v = X4[f];
            uint2 hv = make_uint2(pack_h2(v.x, v.y), pack_h2(v.z, v.w));
            *reinterpret_cast<uint2*>(smem + SM_A + row * ROWB + d * 2) = hv;
        }
        float* hc = (float*)(smem + SM_HC);
        for (int i = t; i < K_CODES; i += 256) hc[i] = -0.5f * g_csq[i];
    }
    __syncthreads();

    uint32_t af[NUM_KS][4];
    {
        uint32_t aAddr = sb + SM_A + (uint32_t)(wr0 + (l & 15)) * ROWB + (uint32_t)(l >> 4) * 16;
#pragma unroll
        for (int ks = 0; ks < NUM_KS; ks++)
            LDSM4(af[ks][0], af[ks][1], af[ks][2], af[ks][3], aAddr + ks * 32);
    }

    float bmA1 = -3.0e38f, bmA2 = -3.0e38f, bmB1 = -3.0e38f, bmB2 = -3.0e38f;
    int bkA = 0, bkB = 0;
    const float* hc = (const float*)(smem + SM_HC);

    for (int c = 0; c < NUM_CHUNKS; c++) {
        float acc[8][4];
#pragma unroll
        for (int nt = 0; nt < 8; nt++)
#pragma unroll
            for (int j = 0; j < 4; j++) acc[nt][j] = 0.f;

        const uint4* bf = reinterpret_cast<const uint4*>(g_Bfrag) + (size_t)c * 8 * 2 * 32 + l;
#pragma unroll
        for (int nt = 0; nt < 8; nt++) {
            uint4 f0 = __ldg(bf + (nt * 2 + 0) * 32);
            uint4 f1 = __ldg(bf + (nt * 2 + 1) * 32);
            MMA16816(acc[nt], af[0], f0.x, f0.y);
            MMA16816(acc[nt], af[1], f0.z, f0.w);
            MMA16816(acc[nt], af[2], f1.x, f1.y);
            MMA16816(acc[nt], af[3], f1.z, f1.w);
        }

#pragma unroll
        for (int nt = 0; nt < 8; nt++) {
            int k0 = c * CHUNK + nt * 8 + (l & 3) * 2;
            float2 hcv = *reinterpret_cast<const float2*>(hc + k0);
            float v0 = acc[nt][0] + hcv.x, v1 = acc[nt][1] + hcv.y;
            float v2 = acc[nt][2] + hcv.x, v3 = acc[nt][3] + hcv.y;
            if (v0 > bmA1) { bmA2 = bmA1; bmA1 = v0; bkA = k0; }     else bmA2 = fmaxf(bmA2, v0);
            if (v1 > bmA1) { bmA2 = bmA1; bmA1 = v1; bkA = k0 + 1; } else bmA2 = fmaxf(bmA2, v1);
            if (v2 > bmB1) { bmB2 = bmB1; bmB1 = v2; bkB = k0; }     else bmB2 = fmaxf(bmB2, v2);
            if (v3 > bmB1) { bmB2 = bmB1; bmB1 = v3; bkB = k0 + 1; } else bmB2 = fmaxf(bmB2, v3);
        }
    }

#pragma unroll
    for (int off = 1; off <= 2; off <<= 1) {
        float o1, o2; int ok;
        o1 = __shfl_xor_sync(0xffffffffu, bmA1, off);
        o2 = __shfl_xor_sync(0xffffffffu, bmA2, off);
        ok = __shfl_xor_sync(0xffffffffu, bkA, off);
        {
            bool bw = (o1 > bmA1) || (o1 == bmA1 && ok < bkA);
            float n2 = fmaxf(fminf(bmA1, o1), fmaxf(bmA2, o2));
            if (bw) { bmA1 = o1; bkA = ok; }
            bmA2 = n2;
        }
        o1 = __shfl_xor_sync(0xffffffffu, bmB1, off);
        o2 = __shfl_xor_sync(0xffffffffu, bmB2, off);
        ok = __shfl_xor_sync(0xffffffffu, bkB, off);
        {
            bool bw = (o1 > bmB1) || (o1 == bmB1 && ok < bkB);
            float n2 = fmaxf(fminf(bmB1, o1), fmaxf(bmB2, o2));
            if (bw) { bmB1 = o1; bkB = ok; }
            bmB2 = n2;
        }
    }
    if ((l & 3) == 0) {
        int rowA = wr0 + (l >> 2);
        int rowB = rowA + 8;
        best_sh[rowA] = bkA;
        best_sh[rowB] = bkB;
        out_idx[m0 + rowA] = (float)bkA;
        out_idx[m0 + rowB] = (float)bkB;
        if (bmA1 - bmA2 <= TAU) { int a = atomicAdd(&g_namb, 1); g_amb_rows[a] = m0 + rowA; }
        if (bmB1 - bmB2 <= TAU) { int a = atomicAdd(&g_namb, 1); g_amb_rows[a] = m0 + rowB; }
    }
    __syncthreads();

#pragma unroll
    for (int i = 0; i < (M_TILE * D_DIM) / 256; i++) {
        int f = t + i * 256;
        int row = f >> 6, d = f & 63;
        int bk = best_sh[row];
        size_t g = (size_t)(m0 + row) * D_DIM + d;
        float cv = __ldg(&Cb[(size_t)bk * D_DIM + d]);
        float xv = __ldg(&X[g]);
        out_cb[g]  = cv;
        out_res[g] = __fsub_rn(xv, cv);
    }
}

// ---------------- Exact fallback: 4 rows per 128-thread block (R12-measured 35.5us) ----------------
__global__ void __launch_bounds__(128)
vq_fallback_kernel(const float* __restrict__ X, const float* __restrict__ Cb,
                   float* __restrict__ out_idx, float* __restrict__ out_res,
                   float* __restrict__ out_cb) {
    __shared__ float xrow[4][D_DIM];
    __shared__ float xsq_s[4];
    __shared__ int   rowid[4];
    __shared__ float rs[4][4];     // [warp][slot]
    __shared__ int   rk[4][4];
    __shared__ int   bk_sh[4];

    const int t = threadIdx.x;
    const int w = t >> 5, l = t & 31;
    const int n = g_namb;

    for (int base = blockIdx.x * 4; base < n; base += gridDim.x * 4) {
        __syncthreads();   // protect smem from previous iteration
        {
            int j = base + w;
            if (j < n) {
                int row = g_amb_rows[j];
                float xlo = X[(size_t)row * D_DIM + l];
                float xhi = X[(size_t)row * D_DIM + 32 + l];
                float s = __fadd_rn(__fmul_rn(xlo, xlo), __fmul_rn(xhi, xhi));
#pragma unroll
                for (int off = 16; off >= 1; off >>= 1) {
                    float o = __shfl_down_sync(0xffffffffu, s, off);
                    s = __fadd_rn(s, o);
                }
                xrow[w][l] = xlo;
                xrow[w][l + 32] = xhi;
                if (l == 0) { xsq_s[w] = s; rowid[w] = row; }
            } else if (l == 0) {
                rowid[w] = -1;
            }
        }
        __syncthreads();

        float acc[4][8];
#pragma unroll
        for (int r = 0; r < 4; r++)
#pragma unroll
            for (int c = 0; c < 8; c++) acc[r][c] = 0.f;

#pragma unroll 4
        for (int d = 0; d < D_DIM; d++) {
            float x0 = xrow[0][d], x1 = xrow[1][d], x2 = xrow[2][d], x3 = xrow[3][d];
#pragma unroll
            for (int c = 0; c < 8; c++) {
                float cv = __ldg(&g_Ct[d * K_CODES + c * 128 + t]);
                acc[0][c] = fmaf(x0, cv, acc[0][c]);
                acc[1][c] = fmaf(x1, cv, acc[1][c]);
                acc[2][c] = fmaf(x2, cv, acc[2][c]);
                acc[3][c] = fmaf(x3, cv, acc[3][c]);
            }
        }

        float bs[4] = {3.0e38f, 3.0e38f, 3.0e38f, 3.0e38f};
        int   bk[4] = {0, 0, 0, 0};
        float xq0 = xsq_s[0], xq1 = xsq_s[1], xq2 = xsq_s[2], xq3 = xsq_s[3];
#pragma unroll
        for (int c = 0; c < 8; c++) {
            int k = c * 128 + t;
            float cs = __ldg(&g_csq[k]);
            float q0 = __fadd_rn(__fsub_rn(xq0, 2.0f * acc[0][c]), cs);
            float q1 = __fadd_rn(__fsub_rn(xq1, 2.0f * acc[1][c]), cs);
            float q2 = __fadd_rn(__fsub_rn(xq2, 2.0f * acc[2][c]), cs);
            float q3 = __fadd_rn(__fsub_rn(xq3, 2.0f * acc[3][c]), cs);
            if (q0 < bs[0]) { bs[0] = q0; bk[0] = k; }   // k ascending: strict < keeps lowest
            if (q1 < bs[1]) { bs[1] = q1; bk[1] = k; }
            if (q2 < bs[2]) { bs[2] = q2; bk[2] = k; }
            if (q3 < bs[3]) { bs[3] = q3; bk[3] = k; }
        }

#pragma unroll
        for (int r = 0; r < 4; r++) {
#pragma unroll
            for (int off = 16; off; off >>= 1) {
                float os = __shfl_xor_sync(0xffffffffu, bs[r], off);
                int   ok = __shfl_xor_sync(0xffffffffu, bk[r], off);
                if (os < bs[r] || (os == bs[r] && ok < bk[r])) { bs[r] = os; bk[r] = ok; }
            }
            if (l == 0) { rs[w][r] = bs[r]; rk[w][r] = bk[r]; }
        }
        __syncthreads();
        if (t < 4 && rowid[t] >= 0) {
            float fbs = rs[0][t];
            int   fbk = rk[0][t];
#pragma unroll
            for (int wi = 1; wi < 4; wi++) {
                float o = rs[wi][t];
                int  ok = rk[wi][t];
                if (o < fbs || (o == fbs && ok < fbk)) { fbs = o; fbk = ok; }
            }
            bk_sh[t] = fbk;
            out_idx[rowid[t]] = (float)fbk;
        }
        __syncthreads();

#pragma unroll
        for (int i = 0; i < 2; i++) {
            int f = t + i * 128;
            int slot = f >> 6, d = f & 63;
            int row = rowid[slot];
            if (row >= 0) {
                int k1 = bk_sh[slot];
                size_t g = (size_t)row * D_DIM + d;
                float cv = __ldg(&Cb[(size_t)k1 * D_DIM + d]);
                out_cb[g]  = cv;
                out_res[g] = __fsub_rn(xrow[slot][d], cv);
            }
        }
    }
}

// ---------------- Launch ----------------
extern "C" void kernel_launch(void* const* d_in, const int* in_sizes, int n_in,
                              void* d_out, int out_size) {
    const float* X = (const float*)d_in[0];
    const float* C = (const float*)d_in[1];
    float* out_idx = (float*)d_out;
    float* out_res = out_idx + N_ROWS;
    float* out_cb  = out_res + (size_t)N_ROWS * D_DIM;

    cudaFuncSetAttribute(vq_screen_kernel,
                         cudaFuncAttributeMaxDynamicSharedMemorySize, SM_TOTAL);

    prep_csq_kernel<<<(K_CODES + 255) / 256, 256>>>(C);
    prep_transpose_kernel<<<dim3(K_CODES / 32, D_DIM / 32), dim3(32, 8)>>>(C);
    prep_frag_kernel<<<16, 256>>>(C);
    vq_screen_kernel<<<N_ROWS / M_TILE, 256, SM_TOTAL>>>(X, C, out_idx, out_res, out_cb);
    vq_fallback_kernel<<<1024, 128>>>(X, C, out_idx, out_res, out_cb);
}

// round 15
// speedup vs baseline: 1.4339x; 1.0589x over previous
#include <cuda_runtime.h>
#include <cuda_fp16.h>
#include <cstdint>

// ---------------- Problem constants ----------------
#define N_ROWS     262144
#define K_CODES    1024
#define D_DIM      64
#define M_TILE     128                  // rows per CTA
#define HCHUNK     32                   // codes per half-chunk
#define NUM_HC     (K_CODES / HCHUNK)   // 32
#define KCOLS      64                   // fp16 codebook cols
#define NUM_KS     (KCOLS / 16)         // 4
#define ROWB       144                  // A smem row stride bytes (LDSM conflict-free)
#define TAU        1.2e-3f              // certification threshold

// ---------------- Static scratch ----------------
__device__ float g_csq[K_CODES];
__device__ float g_Ct[D_DIM * K_CODES];                 // transposed codebook (d-major)
// B in HMMA fragment order: [gtile(128)][half(2)][lane(32)] x uint4
__device__ __align__(16) uint32_t g_Bfrag[(K_CODES / 8) * 2 * 32 * 4];
__device__ int g_namb;
__device__ int g_amb_rows[N_ROWS];

// ---------------- Helpers ----------------
__device__ __forceinline__ uint32_t smem_u32(const void* p) {
    uint32_t a;
    asm("{ .reg .u64 t; cvta.to.shared.u64 t, %1; cvt.u32.u64 %0, t; }" : "=r"(a) : "l"(p));
    return a;
}
#define LDSM4(r0, r1, r2, r3, a)                                                    \
    asm volatile("ldmatrix.sync.aligned.m8n8.x4.shared.b16 {%0,%1,%2,%3}, [%4];"    \
                 : "=r"(r0), "=r"(r1), "=r"(r2), "=r"(r3) : "r"(a))
#define MMA16816(d, a, b0v, b1v)                                                    \
    asm volatile("mma.sync.aligned.m16n8k16.row.col.f32.f16.f16.f32 "               \
                 "{%0,%1,%2,%3},{%4,%5,%6,%7},{%8,%9},{%0,%1,%2,%3};"               \
                 : "+f"((d)[0]), "+f"((d)[1]), "+f"((d)[2]), "+f"((d)[3])           \
                 : "r"((a)[0]), "r"((a)[1]), "r"((a)[2]), "r"((a)[3]),              \
                   "r"(b0v), "r"(b1v))

__device__ __forceinline__ uint32_t pack_h2(float a, float b) {
    __half2 t(__float2half_rn(a), __float2half_rn(b));
    return *reinterpret_cast<uint32_t*>(&t);
}

// ---------------- Exact reference-order arithmetic (bit-validated R3/R5/R6/R8/R12) ----------------
__device__ __forceinline__ float sq_sum_tree64(const float* v) {
    float s[32];
#pragma unroll
    for (int l = 0; l < 32; l++) {
        float a = v[l], b = v[l + 32];
        s[l] = __fadd_rn(__fmul_rn(a, a), __fmul_rn(b, b));
    }
#pragma unroll
    for (int off = 16; off >= 1; off >>= 1)
#pragma unroll
        for (int l = 0; l < 16; l++)
            if (l < off) s[l] = __fadd_rn(s[l], s[l + off]);
    return s[0];
}

// ---------------- Prep A: exact csq (validated tree) + zero amb counter ----------------
__global__ void prep_csq_kernel(const float* __restrict__ Cb) {
    int k = blockIdx.x * blockDim.x + threadIdx.x;
    if (k == 0) g_namb = 0;
    if (k >= K_CODES) return;
    g_csq[k] = sq_sum_tree64(Cb + (size_t)k * D_DIM);
}

// ---------------- Prep B: tiled transpose Cb[k][d] -> g_Ct[d][k] ----------------
__global__ void prep_transpose_kernel(const float* __restrict__ Cb) {
    __shared__ float tile[32][33];
    const int k0 = blockIdx.x * 32;
    const int d0 = blockIdx.y * 32;
    const int x = threadIdx.x, y = threadIdx.y;
#pragma unroll
    for (int j = 0; j < 32; j += 8)
        tile[y + j][x] = Cb[(size_t)(k0 + y + j) * D_DIM + d0 + x];
    __syncthreads();
#pragma unroll
    for (int j = 0; j < 32; j += 8)
        g_Ct[(d0 + y + j) * K_CODES + k0 + x] = tile[x][y + j];
}

// ---------------- Prep C: fp16 codebook in m16n8k16 B-fragment order ----------------
__global__ void prep_frag_kernel(const float* __restrict__ Cb) {
    int tid = blockIdx.x * blockDim.x + threadIdx.x;   // 0..4095
    int gt = tid >> 5, l = tid & 31;
    int code = gt * 8 + (l >> 2);
    int kb = 2 * (l & 3);
    const float* cr = Cb + (size_t)code * D_DIM;
    uint32_t f[8];
#pragma unroll
    for (int ks = 0; ks < 4; ks++) {
        float2 v0 = *reinterpret_cast<const float2*>(cr + ks * 16 + kb);
        float2 v1 = *reinterpret_cast<const float2*>(cr + ks * 16 + kb + 8);
        f[ks * 2 + 0] = pack_h2(v0.x, v0.y);
        f[ks * 2 + 1] = pack_h2(v1.x, v1.y);
    }
    uint4* dst = reinterpret_cast<uint4*>(g_Bfrag);
    dst[(gt * 2 + 0) * 32 + l] = make_uint4(f[0], f[1], f[2], f[3]);
    dst[(gt * 2 + 1) * 32 + l] = make_uint4(f[4], f[5], f[6], f[7]);
}

// ---------------- Screen kernel: half-chunk register diet for 3 CTAs/SM ----------------
#define SM_A   0u                       // 128 x 144B = 18432
#define SM_HC  18432u                   // 1024 f32 = 4096 (-0.5*csq)
#define SM_BK  22528u                   // 128 i32
#define SM_TOTAL 23040u

extern "C" __global__ void __launch_bounds__(256, 3)
vq_screen_kernel(const float* __restrict__ X, const float* __restrict__ Cb,
                 float* __restrict__ out_idx, float* __restrict__ out_res,
                 float* __restrict__ out_cb) {
    extern __shared__ __align__(128) char smem[];
    const uint32_t sb = smem_u32(smem);
    const int t = threadIdx.x;
    const int w = t >> 5, l = t & 31;
    const int wr0 = w * 16;
    const int m0 = blockIdx.x * M_TILE;
    int* best_sh = (int*)(smem + SM_BK);

    {
        const float4* X4 = (const float4*)(X + (size_t)m0 * D_DIM);
#pragma unroll
        for (int i = 0; i < 8; i++) {
            int f = t + i * 256;
            int row = f >> 4, d = (f & 15) * 4;
            float4 v = X4[f];
            uint2 hv = make_uint2(pack_h2(v.x, v.y), pack_h2(v.z, v.w));
            *reinterpret_cast<uint2*>(smem + SM_A + row * ROWB + d * 2) = hv;
        }
        float* hc = (float*)(smem + SM_HC);
        for (int i = t; i < K_CODES; i += 256) hc[i] = -0.5f * g_csq[i];
    }
    __syncthreads();

    uint32_t af[NUM_KS][4];
    {
        uint32_t aAddr = sb + SM_A + (uint32_t)(wr0 + (l & 15)) * ROWB + (uint32_t)(l >> 4) * 16;
#pragma unroll
        for (int ks = 0; ks < NUM_KS; ks++)
            LDSM4(af[ks][0], af[ks][1], af[ks][2], af[ks][3], aAddr + ks * 32);
    }

    float bmA1 = -3.0e38f, bmA2 = -3.0e38f, bmB1 = -3.0e38f, bmB2 = -3.0e38f;
    int bkA = 0, bkB = 0;
    const float* hc = (const float*)(smem + SM_HC);

    // 32 half-chunks of 32 codes: acc[4][4] (16 regs) + 8 live uint4 loads
    for (int cc = 0; cc < NUM_HC; cc++) {
        float acc[4][4];
#pragma unroll
        for (int nt = 0; nt < 4; nt++)
#pragma unroll
            for (int j = 0; j < 4; j++) acc[nt][j] = 0.f;

        const uint4* bf = reinterpret_cast<const uint4*>(g_Bfrag) + (size_t)cc * 4 * 2 * 32 + l;
#pragma unroll
        for (int nt = 0; nt < 4; nt++) {
            uint4 f0 = __ldg(bf + (nt * 2 + 0) * 32);
            uint4 f1 = __ldg(bf + (nt * 2 + 1) * 32);
            MMA16816(acc[nt], af[0], f0.x, f0.y);
            MMA16816(acc[nt], af[1], f0.z, f0.w);
            MMA16816(acc[nt], af[2], f1.x, f1.y);
            MMA16816(acc[nt], af[3], f1.z, f1.w);
        }

        // epilogue: bias + running top-2 (k ascending; strict > keeps lowest k)
#pragma unroll
        for (int nt = 0; nt < 4; nt++) {
            int k0 = cc * HCHUNK + nt * 8 + (l & 3) * 2;
            float2 hcv = *reinterpret_cast<const float2*>(hc + k0);
            float v0 = acc[nt][0] + hcv.x, v1 = acc[nt][1] + hcv.y;
            float v2 = acc[nt][2] + hcv.x, v3 = acc[nt][3] + hcv.y;
            if (v0 > bmA1) { bmA2 = bmA1; bmA1 = v0; bkA = k0; }     else bmA2 = fmaxf(bmA2, v0);
            if (v1 > bmA1) { bmA2 = bmA1; bmA1 = v1; bkA = k0 + 1; } else bmA2 = fmaxf(bmA2, v1);
            if (v2 > bmB1) { bmB2 = bmB1; bmB1 = v2; bkB = k0; }     else bmB2 = fmaxf(bmB2, v2);
            if (v3 > bmB1) { bmB2 = bmB1; bmB1 = v3; bkB = k0 + 1; } else bmB2 = fmaxf(bmB2, v3);
        }
    }

#pragma unroll
    for (int off = 1; off <= 2; off <<= 1) {
        float o1, o2; int ok;
        o1 = __shfl_xor_sync(0xffffffffu, bmA1, off);
        o2 = __shfl_xor_sync(0xffffffffu, bmA2, off);
        ok = __shfl_xor_sync(0xffffffffu, bkA, off);
        {
            bool bw = (o1 > bmA1) || (o1 == bmA1 && ok < bkA);
            float n2 = fmaxf(fminf(bmA1, o1), fmaxf(bmA2, o2));
            if (bw) { bmA1 = o1; bkA = ok; }
            bmA2 = n2;
        }
        o1 = __shfl_xor_sync(0xffffffffu, bmB1, off);
        o2 = __shfl_xor_sync(0xffffffffu, bmB2, off);
        ok = __shfl_xor_sync(0xffffffffu, bkB, off);
        {
            bool bw = (o1 > bmB1) || (o1 == bmB1 && ok < bkB);
            float n2 = fmaxf(fminf(bmB1, o1), fmaxf(bmB2, o2));
            if (bw) { bmB1 = o1; bkB = ok; }
            bmB2 = n2;
        }
    }
    if ((l & 3) == 0) {
        int rowA = wr0 + (l >> 2);
        int rowB = rowA + 8;
        best_sh[rowA] = bkA;
        best_sh[rowB] = bkB;
        out_idx[m0 + rowA] = (float)bkA;
        out_idx[m0 + rowB] = (float)bkB;
        if (bmA1 - bmA2 <= TAU) { int a = atomicAdd(&g_namb, 1); g_amb_rows[a] = m0 + rowA; }
        if (bmB1 - bmB2 <= TAU) { int a = atomicAdd(&g_namb, 1); g_amb_rows[a] = m0 + rowB; }
    }
    __syncthreads();

#pragma unroll
    for (int i = 0; i < (M_TILE * D_DIM) / 256; i++) {
        int f = t + i * 256;
        int row = f >> 6, d = f & 63;
        int bk = best_sh[row];
        size_t g = (size_t)(m0 + row) * D_DIM + d;
        float cv = __ldg(&Cb[(size_t)bk * D_DIM + d]);
        float xv = __ldg(&X[g]);
        out_cb[g]  = cv;
        out_res[g] = __fsub_rn(xv, cv);
    }
}

// ---------------- Exact fallback: 4 rows per 128-thread block (R12-measured 35.5us) ----------------
__global__ void __launch_bounds__(128)
vq_fallback_kernel(const float* __restrict__ X, const float* __restrict__ Cb,
                   float* __restrict__ out_idx, float* __restrict__ out_res,
                   float* __restrict__ out_cb) {
    __shared__ float xrow[4][D_DIM];
    __shared__ float xsq_s[4];
    __shared__ int   rowid[4];
    __shared__ float rs[4][4];     // [warp][slot]
    __shared__ int   rk[4][4];
    __shared__ int   bk_sh[4];

    const int t = threadIdx.x;
    const int w = t >> 5, l = t & 31;
    const int n = g_namb;

    for (int base = blockIdx.x * 4; base < n; base += gridDim.x * 4) {
        __syncthreads();   // protect smem from previous iteration
        {
            int j = base + w;
            if (j < n) {
                int row = g_amb_rows[j];
                float xlo = X[(size_t)row * D_DIM + l];
                float xhi = X[(size_t)row * D_DIM + 32 + l];
                float s = __fadd_rn(__fmul_rn(xlo, xlo), __fmul_rn(xhi, xhi));
#pragma unroll
                for (int off = 16; off >= 1; off >>= 1) {
                    float o = __shfl_down_sync(0xffffffffu, s, off);
                    s = __fadd_rn(s, o);
                }
                xrow[w][l] = xlo;
                xrow[w][l + 32] = xhi;
                if (l == 0) { xsq_s[w] = s; rowid[w] = row; }
            } else if (l == 0) {
                rowid[w] = -1;
            }
        }
        __syncthreads();

        float acc[4][8];
#pragma unroll
        for (int r = 0; r < 4; r++)
#pragma unroll
            for (int c = 0; c < 8; c++) acc[r][c] = 0.f;

#pragma unroll 4
        for (int d = 0; d < D_DIM; d++) {
            float x0 = xrow[0][d], x1 = xrow[1][d], x2 = xrow[2][d], x3 = xrow[3][d];
#pragma unroll
            for (int c = 0; c < 8; c++) {
                float cv = __ldg(&g_Ct[d * K_CODES + c * 128 + t]);
                acc[0][c] = fmaf(x0, cv, acc[0][c]);
                acc[1][c] = fmaf(x1, cv, acc[1][c]);
                acc[2][c] = fmaf(x2, cv, acc[2][c]);
                acc[3][c] = fmaf(x3, cv, acc[3][c]);
            }
        }

        float bs[4] = {3.0e38f, 3.0e38f, 3.0e38f, 3.0e38f};
        int   bk[4] = {0, 0, 0, 0};
        float xq0 = xsq_s[0], xq1 = xsq_s[1], xq2 = xsq_s[2], xq3 = xsq_s[3];
#pragma unroll
        for (int c = 0; c < 8; c++) {
            int k = c * 128 + t;
            float cs = __ldg(&g_csq[k]);
            float q0 = __fadd_rn(__fsub_rn(xq0, 2.0f * acc[0][c]), cs);
            float q1 = __fadd_rn(__fsub_rn(xq1, 2.0f * acc[1][c]), cs);
            float q2 = __fadd_rn(__fsub_rn(xq2, 2.0f * acc[2][c]), cs);
            float q3 = __fadd_rn(__fsub_rn(xq3, 2.0f * acc[3][c]), cs);
            if (q0 < bs[0]) { bs[0] = q0; bk[0] = k; }   // k ascending: strict < keeps lowest
            if (q1 < bs[1]) { bs[1] = q1; bk[1] = k; }
            if (q2 < bs[2]) { bs[2] = q2; bk[2] = k; }
            if (q3 < bs[3]) { bs[3] = q3; bk[3] = k; }
        }

#pragma unroll
        for (int r = 0; r < 4; r++) {
#pragma unroll
            for (int off = 16; off; off >>= 1) {
                float os = __shfl_xor_sync(0xffffffffu, bs[r], off);
                int   ok = __shfl_xor_sync(0xffffffffu, bk[r], off);
                if (os < bs[r] || (os == bs[r] && ok < bk[r])) { bs[r] = os; bk[r] = ok; }
            }
            if (l == 0) { rs[w][r] = bs[r]; rk[w][r] = bk[r]; }
        }
        __syncthreads();
        if (t < 4 && rowid[t] >= 0) {
            float fbs = rs[0][t];
            int   fbk = rk[0][t];
#pragma unroll
            for (int wi = 1; wi < 4; wi++) {
                float o = rs[wi][t];
                int  ok = rk[wi][t];
                if (o < fbs || (o == fbs && ok < fbk)) { fbs = o; fbk = ok; }
            }
            bk_sh[t] = fbk;
            out_idx[rowid[t]] = (float)fbk;
        }
        __syncthreads();

#pragma unroll
        for (int i = 0; i < 2; i++) {
            int f = t + i * 128;
            int slot = f >> 6, d = f & 63;
            int row = rowid[slot];
            if (row >= 0) {
                int k1 = bk_sh[slot];
                size_t g = (size_t)row * D_DIM + d;
                float cv = __ldg(&Cb[(size_t)k1 * D_DIM + d]);
                out_cb[g]  = cv;
                out_res[g] = __fsub_rn(xrow[slot][d], cv);
            }
        }
    }
}

// ---------------- Launch ----------------
extern "C" void kernel_launch(void* const* d_in, const int* in_sizes, int n_in,
                              void* d_out, int out_size) {
    const float* X = (const float*)d_in[0];
    const float* C = (const float*)d_in[1];
    float* out_idx = (float*)d_out;
    float* out_res = out_idx + N_ROWS;
    float* out_cb  = out_res + (size_t)N_ROWS * D_DIM;

    cudaFuncSetAttribute(vq_screen_kernel,
                         cudaFuncAttributeMaxDynamicSharedMemorySize, SM_TOTAL);

    prep_csq_kernel<<<(K_CODES + 255) / 256, 256>>>(C);
    prep_transpose_kernel<<<dim3(K_CODES / 32, D_DIM / 32), dim3(32, 8)>>>(C);
    prep_frag_kernel<<<16, 256>>>(C);
    vq_screen_kernel<<<N_ROWS / M_TILE, 256, SM_TOTAL>>>(X, C, out_idx, out_res, out_cb);
    vq_fallback_kernel<<<1024, 128>>>(X, C, out_idx, out_res, out_cb);
}

// round 17
// speedup vs baseline: 1.4962x; 1.0435x over previous
#include <cuda_runtime.h>
#include <cuda_fp16.h>
#include <cstdint>

// ---------------- Problem constants ----------------
#define N_ROWS     262144
#define K_CODES    1024
#define D_DIM      64
#define M_TILE     128                  // rows per CTA
#define HCHUNK     32                   // codes per half-chunk
#define NUM_HC     (K_CODES / HCHUNK)   // 32
#define KCOLS      64                   // fp16 codebook cols
#define NUM_KS     (KCOLS / 16)         // 4
#define ROWB       144                  // A smem row stride bytes (LDSM conflict-free)
#define TAU_Q      1.35e-3f             // certification threshold (screen err + key quantization)
#define KEYMASK    0xFFFFFC00

// ---------------- Static scratch ----------------
__device__ float g_csq[K_CODES];
__device__ float g_Ct[D_DIM * K_CODES];                 // transposed codebook (d-major)
// B in HMMA fragment order: [gtile(128)][half(2)][lane(32)] x uint4
__device__ __align__(16) uint32_t g_Bfrag[(K_CODES / 8) * 2 * 32 * 4];
__device__ int g_namb;
__device__ int g_amb_rows[N_ROWS];

// ---------------- Helpers ----------------
__device__ __forceinline__ uint32_t smem_u32(const void* p) {
    uint32_t a;
    asm("{ .reg .u64 t; cvta.to.shared.u64 t, %1; cvt.u32.u64 %0, t; }" : "=r"(a) : "l"(p));
    return a;
}
#define LDSM4(r0, r1, r2, r3, a)                                                    \
    asm volatile("ldmatrix.sync.aligned.m8n8.x4.shared.b16 {%0,%1,%2,%3}, [%4];"    \
                 : "=r"(r0), "=r"(r1), "=r"(r2), "=r"(r3) : "r"(a))
#define MMA16816(d, a, b0v, b1v)                                                    \
    asm volatile("mma.sync.aligned.m16n8k16.row.col.f32.f16.f16.f32 "               \
                 "{%0,%1,%2,%3},{%4,%5,%6,%7},{%8,%9},{%0,%1,%2,%3};"               \
                 : "+f"((d)[0]), "+f"((d)[1]), "+f"((d)[2]), "+f"((d)[3])           \
                 : "r"((a)[0]), "r"((a)[1]), "r"((a)[2]), "r"((a)[3]),              \
                   "r"(b0v), "r"(b1v))

__device__ __forceinline__ uint32_t pack_h2(float a, float b) {
    __half2 t(__float2half_rn(a), __float2half_rn(b));
    return *reinterpret_cast<uint32_t*>(&t);
}
// packed key: quantized score bits | inverted index (lowest k wins ties via max)
__device__ __forceinline__ int mk_key(float v, int kinv) {
    return (__float_as_int(v) & KEYMASK) | kinv;
}
// second-max chain update (signed int order; compute with OLD k1)
__device__ __forceinline__ void key_upd(int& k1, int& k2, int key) {
    int m = min(k1, key);
    k2 = max(k2, m);
    k1 = max(k1, key);
}

// ---------------- Exact reference-order arithmetic (bit-validated R3/R5/R6/R8/R12) ----------------
__device__ __forceinline__ float sq_sum_tree64(const float* v) {
    float s[32];
#pragma unroll
    for (int l = 0; l < 32; l++) {
        float a = v[l], b = v[l + 32];
        s[l] = __fadd_rn(__fmul_rn(a, a), __fmul_rn(b, b));
    }
#pragma unroll
    for (int off = 16; off >= 1; off >>= 1)
#pragma unroll
        for (int l = 0; l < 16; l++)
            if (l < off) s[l] = __fadd_rn(s[l], s[l + off]);
    return s[0];
}

// ---------------- Prep A: exact csq (validated tree) + zero amb counter ----------------
__global__ void prep_csq_kernel(const float* __restrict__ Cb) {
    int k = blockIdx.x * blockDim.x + threadIdx.x;
    if (k == 0) g_namb = 0;
    if (k >= K_CODES) return;
    g_csq[k] = sq_sum_tree64(Cb + (size_t)k * D_DIM);
}

// ---------------- Prep B: tiled transpose Cb[k][d] -> g_Ct[d][k] ----------------
__global__ void prep_transpose_kernel(const float* __restrict__ Cb) {
    __shared__ float tile[32][33];
    const int k0 = blockIdx.x * 32;
    const int d0 = blockIdx.y * 32;
    const int x = threadIdx.x, y = threadIdx.y;
#pragma unroll
    for (int j = 0; j < 32; j += 8)
        tile[y + j][x] = Cb[(size_t)(k0 + y + j) * D_DIM + d0 + x];
    __syncthreads();
#pragma unroll
    for (int j = 0; j < 32; j += 8)
        g_Ct[(d0 + y + j) * K_CODES + k0 + x] = tile[x][y + j];
}

// ---------------- Prep C: fp16 codebook in m16n8k16 B-fragment order ----------------
__global__ void prep_frag_kernel(const float* __restrict__ Cb) {
    int tid = blockIdx.x * blockDim.x + threadIdx.x;   // 0..4095
    int gt = tid >> 5, l = tid & 31;
    int code = gt * 8 + (l >> 2);
    int kb = 2 * (l & 3);
    const float* cr = Cb + (size_t)code * D_DIM;
    uint32_t f[8];
#pragma unroll
    for (int ks = 0; ks < 4; ks++) {
        float2 v0 = *reinterpret_cast<const float2*>(cr + ks * 16 + kb);
        float2 v1 = *reinterpret_cast<const float2*>(cr + ks * 16 + kb + 8);
        f[ks * 2 + 0] = pack_h2(v0.x, v0.y);
        f[ks * 2 + 1] = pack_h2(v1.x, v1.y);
    }
    uint4* dst = reinterpret_cast<uint4*>(g_Bfrag);
    dst[(gt * 2 + 0) * 32 + l] = make_uint4(f[0], f[1], f[2], f[3]);
    dst[(gt * 2 + 1) * 32 + l] = make_uint4(f[4], f[5], f[6], f[7]);
}

// ---------------- Screen kernel: branchless packed-key top-2 ----------------
#define SM_A   0u                       // 128 x 144B = 18432
#define SM_HC  18432u                   // 1024 f32 = 4096 (-0.5*csq)
#define SM_BK  22528u                   // 128 i32
#define SM_TOTAL 23040u

extern "C" __global__ void __launch_bounds__(256, 3)
vq_screen_kernel(const float* __restrict__ X, const float* __restrict__ Cb,
                 float* __restrict__ out_idx, float* __restrict__ out_res,
                 float* __restrict__ out_cb) {
    extern __shared__ __align__(128) char smem[];
    const uint32_t sb = smem_u32(smem);
    const int t = threadIdx.x;
    const int w = t >> 5, l = t & 31;
    const int wr0 = w * 16;
    const int m0 = blockIdx.x * M_TILE;
    int* best_sh = (int*)(smem + SM_BK);

    {
        const float4* X4 = (const float4*)(X + (size_t)m0 * D_DIM);
#pragma unroll
        for (int i = 0; i < 8; i++) {
            int f = t + i * 256;
            int row = f >> 4, d = (f & 15) * 4;
            float4 v = X4[f];
            uint2 hv = make_uint2(pack_h2(v.x, v.y), pack_h2(v.z, v.w));
            *reinterpret_cast<uint2*>(smem + SM_A + row * ROWB + d * 2) = hv;
        }
        float* hc = (float*)(smem + SM_HC);
        for (int i = t; i < K_CODES; i += 256) hc[i] = -0.5f * g_csq[i];
    }
    __syncthreads();

    uint32_t af[NUM_KS][4];
    {
        uint32_t aAddr = sb + SM_A + (uint32_t)(wr0 + (l & 15)) * ROWB + (uint32_t)(l >> 4) * 16;
#pragma unroll
        for (int ks = 0; ks < NUM_KS; ks++)
            LDSM4(af[ks][0], af[ks][1], af[ks][2], af[ks][3], aAddr + ks * 32);
    }

    // packed-key top-2 state per row slot (rowA = wr0+(l>>2), rowB = rowA+8)
    int kA1 = 0x80000000, kA2 = 0x80000000;
    int kB1 = 0x80000000, kB2 = 0x80000000;
    const float* hc = (const float*)(smem + SM_HC);

    for (int cc = 0; cc < NUM_HC; cc++) {
        float acc[4][4];
#pragma unroll
        for (int nt = 0; nt < 4; nt++)
#pragma unroll
            for (int j = 0; j < 4; j++) acc[nt][j] = 0.f;

        const uint4* bf = reinterpret_cast<const uint4*>(g_Bfrag) + (size_t)cc * 4 * 2 * 32 + l;
#pragma unroll
        for (int nt = 0; nt < 4; nt++) {
            uint4 f0 = __ldg(bf + (nt * 2 + 0) * 32);
            uint4 f1 = __ldg(bf + (nt * 2 + 1) * 32);
            MMA16816(acc[nt], af[0], f0.x, f0.y);
            MMA16816(acc[nt], af[1], f0.z, f0.w);
            MMA16816(acc[nt], af[2], f1.x, f1.y);
            MMA16816(acc[nt], af[3], f1.z, f1.w);
        }

        // epilogue: bias + packed-key top-2 (branchless; lowest k on quantized ties)
#pragma unroll
        for (int nt = 0; nt < 4; nt++) {
            int k0 = cc * HCHUNK + nt * 8 + (l & 3) * 2;
            int kinv0 = 1023 - k0;
            float2 hcv = *reinterpret_cast<const float2*>(hc + k0);
            key_upd(kA1, kA2, mk_key(acc[nt][0] + hcv.x, kinv0));
            key_upd(kA1, kA2, mk_key(acc[nt][1] + hcv.y, kinv0 - 1));
            key_upd(kB1, kB2, mk_key(acc[nt][2] + hcv.x, kinv0));
            key_upd(kB1, kB2, mk_key(acc[nt][3] + hcv.y, kinv0 - 1));
        }
    }

    // ---- merge across the 4 lanes of each quad (int domain) ----
#pragma unroll
    for (int off = 1; off <= 2; off <<= 1) {
        int o1, o2;
        o1 = __shfl_xor_sync(0xffffffffu, kA1, off);
        o2 = __shfl_xor_sync(0xffffffffu, kA2, off);
        kA2 = max(max(kA2, o2), min(kA1, o1));
        kA1 = max(kA1, o1);
        o1 = __shfl_xor_sync(0xffffffffu, kB1, off);
        o2 = __shfl_xor_sync(0xffffffffu, kB2, off);
        kB2 = max(max(kB2, o2), min(kB1, o1));
        kB1 = max(kB1, o1);
    }
    if ((l & 3) == 0) {
        int rowA = wr0 + (l >> 2);
        int rowB = rowA + 8;
        int bkA = 1023 - (kA1 & 1023);
        int bkB = 1023 - (kB1 & 1023);
        best_sh[rowA] = bkA;
        best_sh[rowB] = bkB;
        out_idx[m0 + rowA] = (float)bkA;
        out_idx[m0 + rowB] = (float)bkB;
        float gA = __int_as_float(kA1 & KEYMASK) - __int_as_float(kA2 & KEYMASK);
        float gB = __int_as_float(kB1 & KEYMASK) - __int_as_float(kB2 & KEYMASK);
        if (gA <= TAU_Q) { int a = atomicAdd(&g_namb, 1); g_amb_rows[a] = m0 + rowA; }
        if (gB <= TAU_Q) { int a = atomicAdd(&g_namb, 1); g_amb_rows[a] = m0 + rowB; }
    }
    __syncthreads();

#pragma unroll
    for (int i = 0; i < (M_TILE * D_DIM) / 256; i++) {
        int f = t + i * 256;
        int row = f >> 6, d = f & 63;
        int bk = best_sh[row];
        size_t g = (size_t)(m0 + row) * D_DIM + d;
        float cv = __ldg(&Cb[(size_t)bk * D_DIM + d]);
        float xv = __ldg(&X[g]);
        out_cb[g]  = cv;
        out_res[g] = __fsub_rn(xv, cv);
    }
}

// ---------------- Exact fallback: 4 rows per 128-thread block (R12-measured 35.5us) ----------------
__global__ void __launch_bounds__(128)
vq_fallback_kernel(const float* __restrict__ X, const float* __restrict__ Cb,
                   float* __restrict__ out_idx, float* __restrict__ out_res,
                   float* __restrict__ out_cb) {
    __shared__ float xrow[4][D_DIM];
    __shared__ float xsq_s[4];
    __shared__ int   rowid[4];
    __shared__ float rs[4][4];     // [warp][slot]
    __shared__ int   rk[4][4];
    __shared__ int   bk_sh[4];

    const int t = threadIdx.x;
    const int w = t >> 5, l = t & 31;
    const int n = g_namb;

    for (int base = blockIdx.x * 4; base < n; base += gridDim.x * 4) {
        __syncthreads();   // protect smem from previous iteration
        {
            int j = base + w;
            if (j < n) {
                int row = g_amb_rows[j];
                float xlo = X[(size_t)row * D_DIM + l];
                float xhi = X[(size_t)row * D_DIM + 32 + l];
                float s = __fadd_rn(__fmul_rn(xlo, xlo), __fmul_rn(xhi, xhi));
#pragma unroll
                for (int off = 16; off >= 1; off >>= 1) {
                    float o = __shfl_down_sync(0xffffffffu, s, off);
                    s = __fadd_rn(s, o);
                }
                xrow[w][l] = xlo;
                xrow[w][l + 32] = xhi;
                if (l == 0) { xsq_s[w] = s; rowid[w] = row; }
            } else if (l == 0) {
                rowid[w] = -1;
            }
        }
        __syncthreads();

        float acc[4][8];
#pragma unroll
        for (int r = 0; r < 4; r++)
#pragma unroll
            for (int c = 0; c < 8; c++) acc[r][c] = 0.f;

#pragma unroll 4
        for (int d = 0; d < D_DIM; d++) {
            float x0 = xrow[0][d], x1 = xrow[1][d], x2 = xrow[2][d], x3 = xrow[3][d];
#pragma unroll
            for (int c = 0; c < 8; c++) {
                float cv = __ldg(&g_Ct[d * K_CODES + c * 128 + t]);
                acc[0][c] = fmaf(x0, cv, acc[0][c]);
                acc[1][c] = fmaf(x1, cv, acc[1][c]);
                acc[2][c] = fmaf(x2, cv, acc[2][c]);
                acc[3][c] = fmaf(x3, cv, acc[3][c]);
            }
        }

        float bs[4] = {3.0e38f, 3.0e38f, 3.0e38f, 3.0e38f};
        int   bk[4] = {0, 0, 0, 0};
        float xq0 = xsq_s[0], xq1 = xsq_s[1], xq2 = xsq_s[2], xq3 = xsq_s[3];
#pragma unroll
        for (int c = 0; c < 8; c++) {
            int k = c * 128 + t;
            float cs = __ldg(&g_csq[k]);
            float q0 = __fadd_rn(__fsub_rn(xq0, 2.0f * acc[0][c]), cs);
            float q1 = __fadd_rn(__fsub_rn(xq1, 2.0f * acc[1][c]), cs);
            float q2 = __fadd_rn(__fsub_rn(xq2, 2.0f * acc[2][c]), cs);
            float q3 = __fadd_rn(__fsub_rn(xq3, 2.0f * acc[3][c]), cs);
            if (q0 < bs[0]) { bs[0] = q0; bk[0] = k; }   // k ascending: strict < keeps lowest
            if (q1 < bs[1]) { bs[1] = q1; bk[1] = k; }
            if (q2 < bs[2]) { bs[2] = q2; bk[2] = k; }
            if (q3 < bs[3]) { bs[3] = q3; bk[3] = k; }
        }

#pragma unroll
        for (int r = 0; r < 4; r++) {
#pragma unroll
            for (int off = 16; off; off >>= 1) {
                float os = __shfl_xor_sync(0xffffffffu, bs[r], off);
                int   ok = __shfl_xor_sync(0xffffffffu, bk[r], off);
                if (os < bs[r] || (os == bs[r] && ok < bk[r])) { bs[r] = os; bk[r] = ok; }
            }
            if (l == 0) { rs[w][r] = bs[r]; rk[w][r] = bk[r]; }
        }
        __syncthreads();
        if (t < 4 && rowid[t] >= 0) {
            float fbs = rs[0][t];
            int   fbk = rk[0][t];
#pragma unroll
            for (int wi = 1; wi < 4; wi++) {
                float o = rs[wi][t];
                int  ok = rk[wi][t];
                if (o < fbs || (o == fbs && ok < fbk)) { fbs = o; fbk = ok; }
            }
            bk_sh[t] = fbk;
            out_idx[rowid[t]] = (float)fbk;
        }
        __syncthreads();

#pragma unroll
        for (int i = 0; i < 2; i++) {
            int f = t + i * 128;
            int slot = f >> 6, d = f & 63;
            int row = rowid[slot];
            if (row >= 0) {
                int k1 = bk_sh[slot];
                size_t g = (size_t)row * D_DIM + d;
                float cv = __ldg(&Cb[(size_t)k1 * D_DIM + d]);
                out_cb[g]  = cv;
                out_res[g] = __fsub_rn(xrow[slot][d], cv);
            }
        }
    }
}

// ---------------- Launch ----------------
extern "C" void kernel_launch(void* const* d_in, const int* in_sizes, int n_in,
                              void* d_out, int out_size) {
    const float* X = (const float*)d_in[0];
    const float* C = (const float*)d_in[1];
    float* out_idx = (float*)d_out;
    float* out_res = out_idx + N_ROWS;
    float* out_cb  = out_res + (size_t)N_ROWS * D_DIM;

    cudaFuncSetAttribute(vq_screen_kernel,
                         cudaFuncAttributeMaxDynamicSharedMemorySize, SM_TOTAL);

    prep_csq_kernel<<<(K_CODES + 255) / 256, 256>>>(C);
    prep_transpose_kernel<<<dim3(K_CODES / 32, D_DIM / 32), dim3(32, 8)>>>(C);
    prep_frag_kernel<<<16, 256>>>(C);
    vq_screen_kernel<<<N_ROWS / M_TILE, 256, SM_TOTAL>>>(X, C, out_idx, out_res, out_cb);
    vq_fallback_kernel<<<1024, 128>>>(X, C, out_idx, out_res, out_cb);
}